// round 5
// baseline (speedup 1.0000x reference)
#include <cuda_runtime.h>
#include <math.h>
#include <stdint.h>

#define BATCH 1024
#define C0 512
#define C1 1024
#define K0 100
#define K1 50

#define THREADS 128
#define BLOCKS_PER_SM 8
#define GRID (148 * BLOCKS_PER_SM)            /* 1184, fully resident */
#define TOTAL_WARPS (GRID * 4)                 /* 4736 */

#define WCHUNK_FLOATS 1568                     /* 32*49 floats = 6272 B */
#define WCHUNK_BYTES  (WCHUNK_FLOATS * 4)
#define WCH0 65536                             /* feat0 warp-chunks */
#define WCH1 32768                             /* feat1 warp-chunks */
#define WCHT (WCH0 + WCH1)                     /* 98304 */

#define BPB0 8
#define BPB1 4
#define NHB0 (BATCH / BPB0)                    /* 128 */
#define NHB1 (BATCH / BPB1)                    /* 256 */
#define NHB  (NHB0 + NHB1)                     /* 384 <= resident grid */

/* dynamic smem: pool needs 4*6272=25088; head needs 16384(sp)+4096(slog)+64 */
#define SMEM_DYN 25216

// ---------------- scratch (device globals; no allocation) ----------------
__device__ float g_pooled0[BATCH * C0];
__device__ float g_pooled1[BATCH * C1];
__device__ float g_pnll[NHB];
__device__ float g_pws [NHB];
__device__ int   g_pool_done;   // zero-init; self-reset after finalize
__device__ int   g_head_done;

#define FMA2(acc, a, b) \
    asm("fma.rn.f32x2 %0, %1, %2, %0;" : "+l"(acc) : "l"(a), "l"(b))

// ---------------- head phase (templated on per-block batch / dims) ---------
template<int BPBX, int CX, int KX>
__device__ __forceinline__ void head_block(
        int bid_local, const float* __restrict__ pooled,
        const float* __restrict__ W, const float* __restrict__ bias,
        const int* __restrict__ lut, const float* __restrict__ cw,
        const int* __restrict__ target, int slot,
        float* sp, float* slog, float* s_nll, float* s_ws) {
    const int t = threadIdx.x;
    const int bbase = bid_local * BPBX;

    {   // stage BPBX pooled rows (16 KB) into smem
        const float4* src = reinterpret_cast<const float4*>(pooled + (size_t)bbase * CX);
        float4* dst = reinterpret_cast<float4*>(sp);
        const int n4 = (BPBX * CX) >> 2;
        #pragma unroll
        for (int i = t; i < n4; i += THREADS) dst[i] = src[i];
    }
    __syncthreads();

    float logit[BPBX];
    if (t < KX) {
        uint64_t accA[BPBX], accB[BPBX];
        #pragma unroll
        for (int j = 0; j < BPBX; j++) { accA[j] = 0ull; accB[j] = 0ull; }
        const ulonglong2* w2 = reinterpret_cast<const ulonglong2*>(W + (size_t)t * CX);
        const int C4 = CX >> 2;
        for (int c4 = 0; c4 < C4; c4++) {
            ulonglong2 wv = __ldg(w2 + c4);
            #pragma unroll
            for (int j = 0; j < BPBX; j++) {
                ulonglong2 pv = *reinterpret_cast<const ulonglong2*>(&sp[j * CX + (c4 << 2)]);
                FMA2(accA[j], pv.x, wv.x);
                FMA2(accB[j], pv.y, wv.y);
            }
        }
        float bv = bias[t];
        #pragma unroll
        for (int j = 0; j < BPBX; j++) {
            float ax = __uint_as_float((uint32_t)accA[j]);
            float ay = __uint_as_float((uint32_t)(accA[j] >> 32));
            float bx = __uint_as_float((uint32_t)accB[j]);
            float by = __uint_as_float((uint32_t)(accB[j] >> 32));
            logit[j] = (ax + ay) + (bx + by) + bv;
        }
    }
    #pragma unroll
    for (int j = 0; j < BPBX; j++)
        slog[j * 128 + t] = (t < KX) ? logit[j] : -INFINITY;
    __syncthreads();

    const int warp = t >> 5, lane = t & 31;
    for (int j = warp; j < BPBX; j += 4) {
        float v0 = slog[j * 128 + lane];
        float v1 = slog[j * 128 + lane + 32];
        float v2 = slog[j * 128 + lane + 64];
        float v3 = slog[j * 128 + lane + 96];
        float mx = fmaxf(fmaxf(v0, v1), fmaxf(v2, v3));
        #pragma unroll
        for (int o = 16; o > 0; o >>= 1)
            mx = fmaxf(mx, __shfl_xor_sync(0xffffffffu, mx, o));
        float se = expf(v0 - mx) + expf(v1 - mx) + expf(v2 - mx) + expf(v3 - mx);
        #pragma unroll
        for (int o = 16; o > 0; o >>= 1)
            se += __shfl_xor_sync(0xffffffffu, se, o);
        if (lane == 0) {
            float lse  = mx + logf(se);
            int   bidx = bbase + j;
            int   tc   = lut[target[bidx]];
            float nll  = lse - slog[j * 128 + tc];
            float w    = cw[tc];
            s_nll[j] = w * nll;
            s_ws [j] = w;
        }
    }
    __syncthreads();
    if (t == 0) {
        float pn = 0.f, pw = 0.f;
        #pragma unroll
        for (int j = 0; j < BPBX; j++) { pn += s_nll[j]; pw += s_ws[j]; }
        g_pnll[slot] = pn;
        g_pws [slot] = pw;
    }
}

// ---------------- fused persistent kernel ----------------------------------
__global__ void __launch_bounds__(THREADS, BLOCKS_PER_SM) fused_kernel(
        const float* __restrict__ feat0, const float* __restrict__ feat1,
        const float* __restrict__ W0, const float* __restrict__ b0,
        const float* __restrict__ W1, const float* __restrict__ b1,
        const int*   __restrict__ lut0, const int* __restrict__ lut1,
        const float* __restrict__ cw0, const float* __restrict__ cw1,
        const int*   __restrict__ target, float* __restrict__ out) {
    extern __shared__ __align__(16) char smem[];
    const int t    = threadIdx.x;
    const int bid  = blockIdx.x;
    const int wid  = t >> 5;
    const int lane = t & 31;

    // ======================= POOL PHASE (warp-private streaming) ===========
    {
        float* wbuf = (float*)(smem + wid * WCHUNK_BYTES);
        float4* sw  = (float4*)wbuf;
        const int gwarp = bid * 4 + wid;

        for (int ch = gwarp; ch < WCHT; ch += TOTAL_WARPS) {
            const float* src = (ch < WCH0)
                ? feat0 + (size_t)ch * WCHUNK_FLOATS
                : feat1 + (size_t)(ch - WCH0) * WCHUNK_FLOATS;
            const float4* s4 = reinterpret_cast<const float4*>(src);

            // 392 float4 per warp: two batches (7 + 5) + 8-lane tail
            float4 r[7];
            #pragma unroll
            for (int i = 0; i < 7; i++) r[i] = __ldcs(s4 + i * 32 + lane);
            #pragma unroll
            for (int i = 0; i < 7; i++) sw[i * 32 + lane] = r[i];
            #pragma unroll
            for (int i = 0; i < 5; i++) r[i] = __ldcs(s4 + (7 + i) * 32 + lane);
            float4 tail;
            if (lane < 8) tail = __ldcs(s4 + 384 + lane);
            #pragma unroll
            for (int i = 0; i < 5; i++) sw[(7 + i) * 32 + lane] = r[i];
            if (lane < 8) sw[384 + lane] = tail;
            __syncwarp();

            // lane sums 49 floats at stride-49 (odd -> conflict-free)
            const float* p = wbuf + 49 * lane;
            float s0 = 0.f, s1 = 0.f, s2 = 0.f, s3 = 0.f;
            #pragma unroll
            for (int j = 0; j < 48; j += 4) {
                s0 += p[j]; s1 += p[j + 1]; s2 += p[j + 2]; s3 += p[j + 3];
            }
            float s = (s0 + s1) + (s2 + s3) + p[48];

            if (ch < WCH0) {
                // 4 lanes == one channel row of 196
                s += __shfl_down_sync(0xffffffffu, s, 2);
                s += __shfl_down_sync(0xffffffffu, s, 1);
                if ((lane & 3) == 0)
                    g_pooled0[ch * 8 + (lane >> 2)] = s * (1.0f / 196.0f);
            } else {
                g_pooled1[(ch - WCH0) * 32 + lane] = s * (1.0f / 49.0f);
            }
            __syncwarp();
        }
    }

    // ======================= GRID GATE =======================
    __threadfence();
    __syncthreads();
    if (t == 0) atomicAdd(&g_pool_done, 1);
    if (bid >= NHB) return;          // non-head blocks retire, freeing slots

    if (t == 0) {
        while (atomicAdd(&g_pool_done, 0) < GRID) __nanosleep(200);
    }
    __syncthreads();
    __threadfence();                 // acquire

    // ======================= HEAD PHASE =======================
    float* sp    = (float*)smem;                       // 16 KB
    float* slog  = (float*)(smem + 16384);             // 4 KB
    float* s_nll = slog + 8 * 128;
    float* s_ws  = s_nll + 8;

    if (bid < NHB0) {
        head_block<BPB0, C0, K0>(bid, g_pooled0, W0, b0, lut0, cw0, target,
                                 bid, sp, slog, s_nll, s_ws);
    } else {
        head_block<BPB1, C1, K1>(bid - NHB0, g_pooled1, W1, b1, lut1, cw1, target,
                                 bid, sp, slog, s_nll, s_ws);
    }

    __shared__ int s_last;
    if (t == 0) {
        __threadfence();
        s_last = (atomicAdd(&g_head_done, 1) == NHB - 1);
    }
    __syncthreads();

    // ======================= FINALIZE (last head block) ====================
    if (s_last) {
        __threadfence();
        const int warp = t >> 5, lane = t & 31;
        float n0 = g_pnll[t],        w0 = g_pws[t];                 // head0: 128
        float n1 = g_pnll[128 + t] + g_pnll[256 + t];               // head1: 256
        float w1 = g_pws [128 + t] + g_pws [256 + t];
        #pragma unroll
        for (int o = 16; o > 0; o >>= 1) {
            n0 += __shfl_down_sync(0xffffffffu, n0, o);
            w0 += __shfl_down_sync(0xffffffffu, w0, o);
            n1 += __shfl_down_sync(0xffffffffu, n1, o);
            w1 += __shfl_down_sync(0xffffffffu, w1, o);
        }
        if (lane == 0) {
            slog[warp * 4 + 0] = n0; slog[warp * 4 + 1] = w0;
            slog[warp * 4 + 2] = n1; slog[warp * 4 + 3] = w1;
        }
        __syncthreads();
        if (t == 0) {
            float a = 0.f, b = 0.f, c = 0.f, d = 0.f;
            #pragma unroll
            for (int w = 0; w < 4; w++) {
                a += slog[w * 4 + 0]; b += slog[w * 4 + 1];
                c += slog[w * 4 + 2]; d += slog[w * 4 + 3];
            }
            out[0] = a / b + c / d;
            g_pool_done = 0;      // reset gates for next graph replay
            g_head_done = 0;
        }
    }
}

// ---------------- launch ----------------------------------------------------
extern "C" void kernel_launch(void* const* d_in, const int* in_sizes, int n_in,
                              void* d_out, int out_size) {
    const float* feat0  = (const float*)d_in[0];
    const float* feat1  = (const float*)d_in[1];
    const float* W0     = (const float*)d_in[2];
    const float* b0     = (const float*)d_in[3];
    const float* W1     = (const float*)d_in[4];
    const float* b1     = (const float*)d_in[5];
    const int*   lut0   = (const int*)  d_in[6];
    const int*   lut1   = (const int*)  d_in[7];
    const float* cw0    = (const float*)d_in[8];
    const float* cw1    = (const float*)d_in[9];
    const int*   target = (const int*)  d_in[10];

    fused_kernel<<<GRID, THREADS, SMEM_DYN>>>(
        feat0, feat1, W0, b0, W1, b1, lut0, lut1, cw0, cw1, target,
        (float*)d_out);
}